// round 6
// baseline (speedup 1.0000x reference)
#include <cuda_runtime.h>

// ---------------- sizes ----------------
#define NB 16
#define CH 64
#define SS 256
#define M0 16
#define NMODE 32
#define PLANE (SS*SS)
#define SZH (NB*CH*PLANE)

typedef unsigned long long u64;

// ---------------- f32x2 helpers ----------------
__device__ __forceinline__ u64 fma2(u64 a, u64 b, u64 c) {
    u64 d;
    asm("fma.rn.f32x2 %0, %1, %2, %3;" : "=l"(d) : "l"(a), "l"(b), "l"(c));
    return d;
}
__device__ __forceinline__ float2 unpk(u64 v) {
    unsigned lo, hi;
    asm("mov.b64 {%0, %1}, %2;" : "=r"(lo), "=r"(hi) : "l"(v));
    return make_float2(__uint_as_float(lo), __uint_as_float(hi));
}

// ---------------- device scratch ----------------
__device__ float  g_h[2][SZH];                 // ping-pong activations (b,c,x,y)
__device__ float  g_Ar[NB*CH*M0*SS];           // y-DFT real: [b][c][ky][x]
__device__ float  g_Ai[NB*CH*M0*SS];           // y-DFT imag
__device__ float2 g_ft[NMODE*M0*NB*CH];        // [mode][b][i]
__device__ float2 g_oft[NMODE*M0*NB*CH];       // [mode][b][o]
__device__ float2 g_t [NB*CH*SS*M0];           // [b][o][x][ky]
__device__ float2 g_W [4*NMODE*M0*CH*CH];      // [blk][mode][i][o]
__device__ float  g_tyc[M0*SS];                // cos(2 pi ky y/256)
__device__ float  g_tys[M0*SS];                // -sin(2 pi ky y/256)
__device__ float  g_xc[NMODE*SS];              // cos(2 pi kxp x/256)
__device__ float  g_xs[NMODE*SS];              // sin(2 pi kxp x/256)

// ---------------- trig tables (once per launch) ----------------
__global__ void k_trig() {
    int t = blockIdx.x * blockDim.x + threadIdx.x;
    if (t < M0 * SS) {
        int ky = t >> 8, y = t & 255;
        float s, c;
        sincospif((float)(ky * y) / 128.0f, &s, &c);   // exact integer arg
        g_tyc[t] = c;
        g_tys[t] = -s;
    } else if (t < M0 * SS + NMODE * SS) {
        int k = t - M0 * SS;
        int m = k >> 8, x = k & 255;
        int kxp = (m < 16) ? m : (m - 32);
        float s, c;
        sincospif((float)(kxp * x) / 128.0f, &s, &c);
        g_xc[k] = c;
        g_xs[k] = s;
    }
}

// ---------------- weight re-layout (once per launch) ----------------
__global__ void k_wprep(const float2* __restrict__ w1, const float2* __restrict__ w2) {
    int idx = blockIdx.x * blockDim.x + threadIdx.x;
    int o   = idx & 63;
    int i   = (idx >> 6) & 63;
    int ky  = (idx >> 12) & 15;
    int m   = (idx >> 16) & 31;
    int blk = (idx >> 21);
    const float2* src = (m < 16) ? w1 : w2;
    int mx = (m < 16) ? m : (m - 16);
    g_W[idx] = src[((((long)blk * 64 + i) * 64 + o) * 16 + mx) * 16 + ky];
}

// ---------------- lift ----------------
__global__ void k_lift(const float* __restrict__ x, const float* __restrict__ w0,
                       const float* __restrict__ b0) {
    __shared__ float sw[192];
    __shared__ float sb[64];
    int t = threadIdx.x;
    if (t < 192) sw[t] = w0[t];
    if (t < 64)  sb[t] = b0[t];
    __syncthreads();
    int b = blockIdx.y, xx = blockIdx.x, y = t;
    const float* xp = x + (((long)b * SS + xx) * SS + y) * 3;
    float x0 = xp[0], x1 = xp[1], x2 = xp[2];
    float* out = g_h[0] + (long)b * CH * PLANE + xx * SS + y;
#pragma unroll
    for (int c = 0; c < CH; c++)
        out[(long)c * PLANE] = x0 * sw[c] + x1 * sw[64 + c] + x2 * sw[128 + c] + sb[c];
}

// ---------------- forward DFT over y ----------------
// y-pair packing: accR2 += (v,v')·(c,c'), accI2 += (v,v')·(-s,-s'); end: horizontal add.
// 256 thr = 16 ky x 16 rowgroups x 4 rows; smem rows padded to 258.
#define SMEM_DFTY ((64*258 + 2*16*258)*4)
__global__ void __launch_bounds__(256) k_dfty(int sel) {
    extern __shared__ float sm[];
    float* sh = sm;               // [64][258]
    float* tc = sh + 64 * 258;    // [16][258]
    float* ts = tc + 16 * 258;
    int b = blockIdx.z, c = blockIdx.y, x0 = blockIdx.x * 64;
    const float* src = g_h[sel] + (long)(b * CH + c) * PLANE + (long)x0 * SS;
    for (int k = threadIdx.x; k < 64 * 256; k += 256) {
        int r = k >> 8, y = k & 255;
        sh[r * 258 + y] = src[k];
    }
    for (int k = threadIdx.x; k < 16 * 256; k += 256) {
        int ky = k >> 8, y = k & 255;
        tc[ky * 258 + y] = g_tyc[k];
        ts[ky * 258 + y] = g_tys[k];
    }
    __syncthreads();
    int ky = threadIdx.x & 15, rg = threadIdx.x >> 4;
    const u64* cp = (const u64*)(tc + ky * 258);
    const u64* sp = (const u64*)(ts + ky * 258);
    const u64* v0 = (const u64*)(sh + (rg * 4 + 0) * 258);
    const u64* v1 = (const u64*)(sh + (rg * 4 + 1) * 258);
    const u64* v2 = (const u64*)(sh + (rg * 4 + 2) * 258);
    const u64* v3 = (const u64*)(sh + (rg * 4 + 3) * 258);
    u64 aR0 = 0, aR1 = 0, aR2 = 0, aR3 = 0;
    u64 aI0 = 0, aI1 = 0, aI2 = 0, aI3 = 0;
#pragma unroll 4
    for (int yp = 0; yp < 128; yp++) {
        u64 c2 = cp[yp], s2 = sp[yp];
        u64 w0 = v0[yp]; aR0 = fma2(w0, c2, aR0); aI0 = fma2(w0, s2, aI0);
        u64 w1 = v1[yp]; aR1 = fma2(w1, c2, aR1); aI1 = fma2(w1, s2, aI1);
        u64 w2 = v2[yp]; aR2 = fma2(w2, c2, aR2); aI2 = fma2(w2, s2, aI2);
        u64 w3 = v3[yp]; aR3 = fma2(w3, c2, aR3); aI3 = fma2(w3, s2, aI3);
    }
    const float sc = 1.0f / 65536.0f;
    long base = ((long)((b * CH + c) * M0 + ky)) * SS + x0 + rg * 4;
    float2 r, i;
    r = unpk(aR0); i = unpk(aI0); g_Ar[base + 0] = (r.x + r.y) * sc; g_Ai[base + 0] = (i.x + i.y) * sc;
    r = unpk(aR1); i = unpk(aI1); g_Ar[base + 1] = (r.x + r.y) * sc; g_Ai[base + 1] = (i.x + i.y) * sc;
    r = unpk(aR2); i = unpk(aI2); g_Ar[base + 2] = (r.x + r.y) * sc; g_Ai[base + 2] = (i.x + i.y) * sc;
    r = unpk(aR3); i = unpk(aI3); g_Ar[base + 3] = (r.x + r.y) * sc; g_Ai[base + 3] = (i.x + i.y) * sc;
}

// ---------------- forward DFT over x ----------------
// x-pair packing; ft = sum_x (Ar+iAi)(c - i s): re = Ar c + Ai s ; im = Ai c - Ar s
__global__ void __launch_bounds__(512) k_dftx() {
    __shared__ float sAr[16 * 258];
    __shared__ float sAi[16 * 258];
    int b = blockIdx.y, i = blockIdx.x;
    long abase = (long)((b * CH + i) * M0) * SS;
    for (int k = threadIdx.x; k < 4096; k += 512) {
        int ky = k >> 8, x = k & 255;
        sAr[ky * 258 + x] = g_Ar[abase + k];
        sAi[ky * 258 + x] = g_Ai[abase + k];
    }
    __syncthreads();
    int ky = threadIdx.x & 15, m = threadIdx.x >> 4;
    const u64* arp = (const u64*)(sAr + ky * 258);
    const u64* aip = (const u64*)(sAi + ky * 258);
    const u64* cp = (const u64*)(g_xc + m * 256);
    const u64* sp = (const u64*)(g_xs + m * 256);
    u64 RC = 0, IS = 0, IC = 0, RS = 0;
#pragma unroll 4
    for (int xp = 0; xp < 128; xp++) {
        u64 c2 = cp[xp], s2 = sp[xp];
        u64 ar = arp[xp], ai = aip[xp];
        RC = fma2(ar, c2, RC);
        IS = fma2(ai, s2, IS);
        IC = fma2(ai, c2, IC);
        RS = fma2(ar, s2, RS);
    }
    float2 rc = unpk(RC), is = unpk(IS), ic = unpk(IC), rs = unpk(RS);
    float re = rc.x + rc.y + is.x + is.y;
    float im = ic.x + ic.y - rs.x - rs.y;
    g_ft[(long)(m * M0 + ky) * (NB * CH) + b * CH + i] = make_float2(re, im);
}

// ---------------- per-mode complex channel mix ----------------
__global__ void k_mix(int blk) {
    __shared__ float2 F[NB * CH];
    int mode = blockIdx.x;
    const float2* src = g_ft + (long)mode * (NB * CH);
    for (int k = threadIdx.x; k < NB * CH; k += 256) F[k] = src[k];
    __syncthreads();
    const float2* W = g_W + ((long)blk * (NMODE * M0) + mode) * (CH * CH);
    int o  = threadIdx.x & 63;
    int bg = threadIdx.x >> 6;
    float accr[4] = {0.f, 0.f, 0.f, 0.f};
    float acci[4] = {0.f, 0.f, 0.f, 0.f};
    for (int i = 0; i < CH; i++) {
        float2 w = W[i * CH + o];
#pragma unroll
        for (int bb = 0; bb < 4; bb++) {
            float2 f = F[(bg * 4 + bb) * CH + i];
            accr[bb] += f.x * w.x - f.y * w.y;
            acci[bb] += f.x * w.y + f.y * w.x;
        }
    }
#pragma unroll
    for (int bb = 0; bb < 4; bb++)
        g_oft[(long)mode * (NB * CH) + (bg * 4 + bb) * CH + o] = make_float2(accr[bb], acci[bb]);
}

// ---------------- inverse DFT over x ----------------
__global__ void k_idftx() {
    __shared__ float2 so[NMODE * M0];
    int b = blockIdx.y, o = blockIdx.x;
    for (int k = threadIdx.x; k < NMODE * M0; k += 256)
        so[k] = g_oft[(long)k * (NB * CH) + b * CH + o];
    __syncthreads();
    int x = threadIdx.x;
    float accr[M0], acci[M0];
#pragma unroll
    for (int ky = 0; ky < M0; ky++) { accr[ky] = 0.f; acci[ky] = 0.f; }
    for (int m = 0; m < NMODE; m++) {
        int kxp = (m < 16) ? m : (m - 32);
        float s, c;
        sincospif((float)(kxp * x) / 128.0f, &s, &c);
#pragma unroll
        for (int ky = 0; ky < M0; ky++) {
            float2 a = so[m * M0 + ky];
            accr[ky] += a.x * c - a.y * s;
            acci[ky] += a.x * s + a.y * c;
        }
    }
    float2* dst = g_t + ((long)(b * CH + o) * SS + x) * M0;
#pragma unroll
    for (int ky = 0; ky < M0; ky++) dst[ky] = make_float2(accr[ky], acci[ky]);
}

// ---------------- block epilogue as one K=96 GEMM ----------------
// rows 0..63: conv (A=cw dup, B=h);  64..79: 2*t.x vs cos;  80..95: 2*t.y vs -sin
// 128 thr = 4 warps x 16-o blocks; lane = y-pair; y-tile 128 (2 pair slots).
#define SMEM_FINAL ((96*130 + 96*128 + 64)*4)
__global__ void __launch_bounds__(128) k_final(int sel, const float* __restrict__ cw,
                                               const float* __restrict__ cb, int relu) {
    extern __shared__ float sm[];
    float* Bm  = sm;                 // [96][130]
    float* Ad  = Bm + 96 * 130;      // [96][128] dup pairs
    float* cbs = Ad + 96 * 128;
    int t = threadIdx.x;
    int b = blockIdx.z, xx = blockIdx.y, yb = blockIdx.x * 128;
    const float* hin = g_h[sel];

    for (int idx = t; idx < 64 * 128; idx += 128) {
        int i = idx >> 7, yl = idx & 127;
        Bm[i * 130 + yl] = hin[(long)(b * CH + i) * PLANE + xx * SS + yb + yl];
    }
    for (int idx = t; idx < 16 * 128; idx += 128) {
        int ky = idx >> 7, yl = idx & 127;
        Bm[(64 + ky) * 130 + yl] = g_tyc[ky * 256 + yb + yl];
        Bm[(80 + ky) * 130 + yl] = g_tys[ky * 256 + yb + yl];
    }
    for (int idx = t; idx < 4096; idx += 128) {
        int o = idx >> 6, i = idx & 63;
        float w = cw[idx];
        Ad[i * 128 + 2 * o] = w;
        Ad[i * 128 + 2 * o + 1] = w;
    }
    for (int idx = t; idx < 1024; idx += 128) {
        int o = idx >> 4, ky = idx & 15;
        float2 v = g_t[((long)(b * CH + o) * SS + xx) * M0 + ky];
        float f = ky ? 2.f : 1.f;
        Ad[(64 + ky) * 128 + 2 * o] = f * v.x;
        Ad[(64 + ky) * 128 + 2 * o + 1] = f * v.x;
        Ad[(80 + ky) * 128 + 2 * o] = f * v.y;
        Ad[(80 + ky) * 128 + 2 * o + 1] = f * v.y;
    }
    if (t < 64) cbs[t] = cb[t];
    __syncthreads();

    int wid = t >> 5, lane = t & 31;
    int ob = wid * 16;
    u64 acc0[16], acc1[16];
#pragma unroll
    for (int oo = 0; oo < 16; oo++) { acc0[oo] = 0; acc1[oo] = 0; }

#pragma unroll 2
    for (int k = 0; k < 96; k++) {
        u64 b0 = *(const u64*)&Bm[k * 130 + 2 * lane];
        u64 b1 = *(const u64*)&Bm[k * 130 + 64 + 2 * lane];
        const u64* ap = (const u64*)&Ad[k * 128 + 2 * ob];
#pragma unroll
        for (int oo = 0; oo < 16; oo++) {
            u64 a = ap[oo];
            acc0[oo] = fma2(a, b0, acc0[oo]);
            acc1[oo] = fma2(a, b1, acc1[oo]);
        }
    }
    float* hout = g_h[sel ^ 1];
#pragma unroll
    for (int oo = 0; oo < 16; oo++) {
        float bias = cbs[ob + oo];
        long obase = (long)(b * CH + ob + oo) * PLANE + xx * SS + yb + 2 * lane;
        float2 v0 = unpk(acc0[oo]);
        v0.x += bias; v0.y += bias;
        if (relu) { v0.x = fmaxf(v0.x, 0.f); v0.y = fmaxf(v0.y, 0.f); }
        *(float2*)&hout[obase] = v0;
        float2 v1 = unpk(acc1[oo]);
        v1.x += bias; v1.y += bias;
        if (relu) { v1.x = fmaxf(v1.x, 0.f); v1.y = fmaxf(v1.y, 0.f); }
        *(float2*)&hout[obase + 64] = v1;
    }
}

// ---------------- fused fc1 + relu + fc2 ----------------
// j-pair packed acc (w1 pairs natural, broadcast); h dup'd (33KB).
// 256 thr = 8 warps x 32-j blocks; lane = y; y-tile 64 (2 slots: lane, lane+32).
#define SMEM_FC ((64*130 + 16384 + 256 + 256 + 64)*4)
__global__ void __launch_bounds__(256) k_fc(int sel, const float* __restrict__ fc1w,
                                            const float* __restrict__ fc1b,
                                            const float* __restrict__ fc2w,
                                            const float* __restrict__ fc2b,
                                            float* __restrict__ out) {
    extern __shared__ float sm[];
    float* hd   = sm;                // [64][130] dup pairs
    float* w1s  = hd + 64 * 130;     // [64][256]
    float* b1s  = w1s + 16384;
    float* f2s  = b1s + 256;
    float* sred = f2s + 256;
    int t = threadIdx.x;
    int b = blockIdx.z, xx = blockIdx.y, yb = blockIdx.x * 64;
    const float* hin = g_h[sel];

    for (int idx = t; idx < 4096; idx += 256) {
        int c = idx >> 6, yl = idx & 63;
        float v = hin[(long)(b * CH + c) * PLANE + xx * SS + yb + yl];
        hd[c * 130 + 2 * yl] = v;
        hd[c * 130 + 2 * yl + 1] = v;
    }
    for (int idx = t; idx < 16384; idx += 256) w1s[idx] = fc1w[idx];
    if (t < 256) { b1s[t] = fc1b[t]; f2s[t] = fc2w[t]; }
    if (t < 64)  sred[t] = fc2b[0];
    __syncthreads();

    int wid = t >> 5, lane = t & 31;
    int jb = wid * 32;
    u64 acc0[16], acc1[16];
#pragma unroll
    for (int jp = 0; jp < 16; jp++) {
        u64 bi = *(const u64*)&b1s[jb + 2 * jp];
        acc0[jp] = bi;
        acc1[jp] = bi;
    }
#pragma unroll 2
    for (int c = 0; c < CH; c++) {
        u64 h0 = *(const u64*)&hd[c * 130 + 2 * lane];
        u64 h1 = *(const u64*)&hd[c * 130 + 64 + 2 * lane];
        const u64* wp = (const u64*)&w1s[c * 256 + jb];
#pragma unroll
        for (int jp = 0; jp < 16; jp++) {
            u64 w = wp[jp];
            acc0[jp] = fma2(w, h0, acc0[jp]);
            acc1[jp] = fma2(w, h1, acc1[jp]);
        }
    }
    float p0 = 0.f, p1 = 0.f;
#pragma unroll
    for (int jp = 0; jp < 16; jp++) {
        float fa = f2s[jb + 2 * jp], fb = f2s[jb + 2 * jp + 1];
        float2 v0 = unpk(acc0[jp]);
        p0 += fmaxf(v0.x, 0.f) * fa + fmaxf(v0.y, 0.f) * fb;
        float2 v1 = unpk(acc1[jp]);
        p1 += fmaxf(v1.x, 0.f) * fa + fmaxf(v1.y, 0.f) * fb;
    }
    atomicAdd(&sred[lane], p0);
    atomicAdd(&sred[32 + lane], p1);
    __syncthreads();
    if (t < 64) out[((long)b * SS + xx) * SS + yb + t] = sred[t];
}

// ---------------- launch ----------------
extern "C" void kernel_launch(void* const* d_in, const int* in_sizes, int n_in,
                              void* d_out, int out_size) {
    const float* x     = (const float*)d_in[0];
    const float* fc0w  = (const float*)d_in[1];
    const float* fc0b  = (const float*)d_in[2];
    const float2* w1   = (const float2*)d_in[3];
    const float2* w2   = (const float2*)d_in[4];
    const float* cw    = (const float*)d_in[5];
    const float* cb    = (const float*)d_in[6];
    const float* fc1w  = (const float*)d_in[7];
    const float* fc1b  = (const float*)d_in[8];
    const float* fc2w  = (const float*)d_in[9];
    const float* fc2b  = (const float*)d_in[10];
    float* out = (float*)d_out;

    cudaFuncSetAttribute(k_dfty,  cudaFuncAttributeMaxDynamicSharedMemorySize, SMEM_DFTY);
    cudaFuncSetAttribute(k_final, cudaFuncAttributeMaxDynamicSharedMemorySize, SMEM_FINAL);
    cudaFuncSetAttribute(k_fc,    cudaFuncAttributeMaxDynamicSharedMemorySize, SMEM_FC);

    k_trig<<<48, 256>>>();
    k_wprep<<<(4 * NMODE * M0 * CH * CH) / 256, 256>>>(w1, w2);
    k_lift<<<dim3(SS, NB), 256>>>(x, fc0w, fc0b);

    int cur = 0;
    for (int blk = 0; blk < 4; blk++) {
        k_dfty<<<dim3(4, CH, NB), 256, SMEM_DFTY>>>(cur);
        k_dftx<<<dim3(CH, NB), 512>>>();
        k_mix<<<NMODE * M0, 256>>>(blk);
        k_idftx<<<dim3(CH, NB), 256>>>();
        k_final<<<dim3(2, SS, NB), 128, SMEM_FINAL>>>(cur, cw + (long)blk * CH * CH,
                                                      cb + blk * CH, blk < 3 ? 1 : 0);
        cur ^= 1;
    }
    k_fc<<<dim3(4, SS, NB), 256, SMEM_FC>>>(cur, fc1w, fc1b, fc2w, fc2b, out);
}

// round 8
// speedup vs baseline: 1.3517x; 1.3517x over previous
#include <cuda_runtime.h>

#define NB 16
#define CH 64
#define SS 256
#define M0 16
#define NMODE 32
#define PLANE (SS*SS)

typedef unsigned long long u64;

__device__ __forceinline__ u64 fma2(u64 a, u64 b, u64 c) {
    u64 d; asm("fma.rn.f32x2 %0,%1,%2,%3;" : "=l"(d) : "l"(a), "l"(b), "l"(c)); return d;
}
__device__ __forceinline__ float2 unpk(u64 v) {
    unsigned lo, hi; asm("mov.b64 {%0,%1},%2;" : "=r"(lo), "=r"(hi) : "l"(v));
    return make_float2(__uint_as_float(lo), __uint_as_float(hi));
}
__device__ __forceinline__ u64 pk(float a, float b) {
    u64 d; asm("mov.b64 %0,{%1,%2};" : "=l"(d) : "r"(__float_as_uint(a)), "r"(__float_as_uint(b)));
    return d;
}
__device__ __forceinline__ void ldsv2(u64& a, u64& b, const void* p) {
    unsigned ad = (unsigned)__cvta_generic_to_shared(p);
    asm("ld.shared.v2.u64 {%0,%1},[%2];" : "=l"(a), "=l"(b) : "r"(ad));
}

// ---------------- device scratch ----------------
// activations channel-pair interleaved: [b][c/2][x][y][2]
__device__ float  g_h2[2][NB*32*SS*SS*2];
__device__ float  g_Ar[NB*CH*M0*SS];           // [b][c][ky][x]
__device__ float  g_Ai[NB*CH*M0*SS];
__device__ float2 g_ft[NMODE*M0*NB*CH];        // [mode][b][i]
__device__ float2 g_oft[NMODE*M0*NB*CH];
__device__ float2 g_t [NB*CH*SS*M0];           // [b][o][x][ky]
__device__ float2 g_W [4*NMODE*M0*CH*CH];      // [blk][mode][i][o]
__device__ float  g_tyc[M0*SS];                // cos(2pi ky y/256)
__device__ float  g_tys[M0*SS];                // -sin
__device__ float  g_xc[NMODE*SS];              // cos(2pi kxp x/256)
__device__ float  g_xs[NMODE*SS];              // sin
__device__ float4 g_ty4[M0*SS];                // (c,c,-s,-s)

// ---------------- trig tables ----------------
__global__ void k_trig() {
    int t = blockIdx.x * blockDim.x + threadIdx.x;
    if (t < M0 * SS) {
        int ky = t >> 8, y = t & 255;
        float s, c;
        sincospif((float)(ky * y) / 128.0f, &s, &c);   // exact integer arg
        g_tyc[t] = c; g_tys[t] = -s;
        g_ty4[t] = make_float4(c, c, -s, -s);
    } else if (t < M0 * SS + NMODE * SS) {
        int k = t - M0 * SS;
        int m = k >> 8, x = k & 255;
        int kxp = (m < 16) ? m : (m - 32);
        float s, c;
        sincospif((float)(kxp * x) / 128.0f, &s, &c);
        g_xc[k] = c; g_xs[k] = s;
    }
}

// ---------------- weight re-layout ----------------
__global__ void k_wprep(const float2* __restrict__ w1, const float2* __restrict__ w2) {
    int idx = blockIdx.x * blockDim.x + threadIdx.x;
    int o = idx & 63, i = (idx >> 6) & 63, ky = (idx >> 12) & 15;
    int m = (idx >> 16) & 31, blk = (idx >> 21);
    const float2* src = (m < 16) ? w1 : w2;
    int mx = (m < 16) ? m : (m - 16);
    g_W[idx] = src[((((long)blk * 64 + i) * 64 + o) * 16 + mx) * 16 + ky];
}

// ---------------- lift: write channel-pair interleaved ----------------
__global__ void k_lift(const float* __restrict__ x, const float* __restrict__ w0,
                       const float* __restrict__ b0) {
    __shared__ float sw[192], sb[64];
    int t = threadIdx.x;
    if (t < 192) sw[t] = w0[t];
    if (t < 64)  sb[t] = b0[t];
    __syncthreads();
    int b = blockIdx.y, xx = blockIdx.x, y = t;
    const float* xp = x + (((long)b * SS + xx) * SS + y) * 3;
    float x0 = xp[0], x1 = xp[1], x2 = xp[2];
    float2* out = (float2*)g_h2[0];
#pragma unroll
    for (int cp = 0; cp < 32; cp++) {
        int c0 = 2 * cp;
        float v0 = x0 * sw[c0]   + x1 * sw[64 + c0]   + x2 * sw[128 + c0]   + sb[c0];
        float v1 = x0 * sw[c0+1] + x1 * sw[64 + c0+1] + x2 * sw[128 + c0+1] + sb[c0+1];
        out[((long)(b * 32 + cp) * SS + xx) * SS + y] = make_float2(v0, v1);
    }
}

// ---------------- forward y-DFT: channel-pair FFMA2 ----------------
// CTA per (cp, b). 256 thr = 8 warps: ky-half (8) x x-group (64 x, 2 per thread).
// y tiled in 8 chunks of 32 staged in smem.
#define SMEM_DFTY (256*33*8 + 16*32*16)
__global__ void __launch_bounds__(256) k_dfty(int sel) {
    extern __shared__ float sm[];
    u64* sh = (u64*)sm;                          // [256 x][33] u64 (pair per y)
    float4* t4 = (float4*)(sm + 256 * 66);       // [16 ky][32 y']
    int b = blockIdx.y, cp = blockIdx.x, t = threadIdx.x;
    const u64* gp = (const u64*)(g_h2[sel]) + (long)(b * 32 + cp) * PLANE;
    int w = t >> 5, lane = t & 31;
    int kyh = (w & 1) * 8, xg = w >> 1;
    int x1 = xg * 64 + lane, x2 = x1 + 32;
    u64 aR[2][8], aI[2][8];
#pragma unroll
    for (int j = 0; j < 2; j++)
#pragma unroll
        for (int k = 0; k < 8; k++) { aR[j][k] = 0; aI[j][k] = 0; }

    for (int yc = 0; yc < 8; yc++) {
#pragma unroll
        for (int i = 0; i < 32; i++) {
            int idx = i * 256 + t, xx = idx >> 5, yy = idx & 31;
            sh[xx * 33 + yy] = gp[xx * 256 + yc * 32 + yy];
        }
#pragma unroll
        for (int i = 0; i < 2; i++) {
            int idx = i * 256 + t, ky = idx >> 5, yy = idx & 31;
            t4[idx] = g_ty4[ky * 256 + yc * 32 + yy];
        }
        __syncthreads();
#pragma unroll 4
        for (int y = 0; y < 32; y++) {
            u64 h1 = sh[x1 * 33 + y], h2v = sh[x2 * 33 + y];
#pragma unroll
            for (int k = 0; k < 8; k++) {
                u64 cc, ss;
                ldsv2(cc, ss, &t4[(kyh + k) * 32 + y]);
                aR[0][k] = fma2(h1, cc, aR[0][k]);  aI[0][k] = fma2(h1, ss, aI[0][k]);
                aR[1][k] = fma2(h2v, cc, aR[1][k]); aI[1][k] = fma2(h2v, ss, aI[1][k]);
            }
        }
        __syncthreads();
    }
    const float sc = 1.0f / 65536.0f;
#pragma unroll
    for (int j = 0; j < 2; j++) {
        int x = j ? x2 : x1;
#pragma unroll
        for (int k = 0; k < 8; k++) {
            int ky = kyh + k;
            long p0 = ((long)((b * 64 + 2 * cp) * 16 + ky)) * 256 + x;
            long p1 = ((long)((b * 64 + 2 * cp + 1) * 16 + ky)) * 256 + x;
            float2 r = unpk(aR[j][k]), ii = unpk(aI[j][k]);
            g_Ar[p0] = r.x * sc;  g_Ar[p1] = r.y * sc;
            g_Ai[p0] = ii.x * sc; g_Ai[p1] = ii.y * sc;
        }
    }
}

// ---------------- forward x-DFT ----------------
__global__ void __launch_bounds__(512) k_dftx() {
    __shared__ float sAr[16 * 258];
    __shared__ float sAi[16 * 258];
    int b = blockIdx.y, i = blockIdx.x;
    long abase = (long)((b * CH + i) * M0) * SS;
    for (int k = threadIdx.x; k < 4096; k += 512) {
        int ky = k >> 8, x = k & 255;
        sAr[ky * 258 + x] = g_Ar[abase + k];
        sAi[ky * 258 + x] = g_Ai[abase + k];
    }
    __syncthreads();
    int ky = threadIdx.x & 15, m = threadIdx.x >> 4;
    const u64* arp = (const u64*)(sAr + ky * 258);
    const u64* aip = (const u64*)(sAi + ky * 258);
    const u64* cp = (const u64*)(g_xc + m * 256);
    const u64* sp = (const u64*)(g_xs + m * 256);
    u64 RC = 0, IS = 0, IC = 0, RS = 0;
#pragma unroll 8
    for (int xp = 0; xp < 128; xp++) {
        u64 c2 = cp[xp], s2 = sp[xp];
        u64 ar = arp[xp], ai = aip[xp];
        RC = fma2(ar, c2, RC); IS = fma2(ai, s2, IS);
        IC = fma2(ai, c2, IC); RS = fma2(ar, s2, RS);
    }
    float2 rc = unpk(RC), is = unpk(IS), ic = unpk(IC), rs = unpk(RS);
    g_ft[(long)(m * M0 + ky) * (NB * CH) + b * CH + i] =
        make_float2(rc.x + rc.y + is.x + is.y, ic.x + ic.y - rs.x - rs.y);
}

// ---------------- per-mode channel mix ----------------
__global__ void k_mix(int blk) {
    __shared__ float2 F[NB * CH];
    int mode = blockIdx.x;
    const float2* src = g_ft + (long)mode * (NB * CH);
    for (int k = threadIdx.x; k < NB * CH; k += 256) F[k] = src[k];
    __syncthreads();
    const float2* W = g_W + ((long)blk * (NMODE * M0) + mode) * (CH * CH);
    int o = threadIdx.x & 63, bg = threadIdx.x >> 6;
    float accr[4] = {0,0,0,0}, acci[4] = {0,0,0,0};
    for (int i = 0; i < CH; i++) {
        float2 w = W[i * CH + o];
#pragma unroll
        for (int bb = 0; bb < 4; bb++) {
            float2 f = F[(bg * 4 + bb) * CH + i];
            accr[bb] += f.x * w.x - f.y * w.y;
            acci[bb] += f.x * w.y + f.y * w.x;
        }
    }
#pragma unroll
    for (int bb = 0; bb < 4; bb++)
        g_oft[(long)mode * (NB * CH) + (bg * 4 + bb) * CH + o] = make_float2(accr[bb], acci[bb]);
}

// ---------------- inverse x-DFT (tables instead of MUFU) ----------------
__global__ void k_idftx() {
    __shared__ float2 so[NMODE * M0];
    int b = blockIdx.y, o = blockIdx.x;
    for (int k = threadIdx.x; k < NMODE * M0; k += 256)
        so[k] = g_oft[(long)k * (NB * CH) + b * CH + o];
    __syncthreads();
    int x = threadIdx.x;
    float accr[M0], acci[M0];
#pragma unroll
    for (int ky = 0; ky < M0; ky++) { accr[ky] = 0.f; acci[ky] = 0.f; }
    for (int m = 0; m < NMODE; m++) {
        float c = g_xc[m * 256 + x], s = g_xs[m * 256 + x];
#pragma unroll
        for (int ky = 0; ky < M0; ky++) {
            float2 a = so[m * M0 + ky];
            accr[ky] += a.x * c - a.y * s;
            acci[ky] += a.x * s + a.y * c;
        }
    }
    float2* dst = g_t + ((long)(b * CH + o) * SS + x) * M0;
#pragma unroll
    for (int ky = 0; ky < M0; ky++) dst[ky] = make_float2(accr[ky], acci[ky]);
}

// ---------------- block epilogue: K=96 GEMM (48 K-pairs), M=64 o, N=128 y ----
// A (wA): rows 0..31 conv i-pairs; 32..39 f*tx ky-pairs; 40..47 f*ty ky-pairs.
// B (Bm): rows = matching K-pair values per y (h pairs / cos pairs / -sin pairs).
#define SMEM_FINAL (48*64*8 + 48*130*8 + 64*4)
__global__ void __launch_bounds__(256) k_final(int sel, const float* __restrict__ cw,
                                               const float* __restrict__ cb, int relu) {
    extern __shared__ float sm[];
    u64* wA = (u64*)sm;                    // [48][64]
    u64* Bm = wA + 48 * 64;                // [48][130] (only 128 used per row)
    float* cbs = (float*)(Bm + 48 * 130);
    int t = threadIdx.x;
    int b = blockIdx.z, xx = blockIdx.y, yb = blockIdx.x * 128;

    const u64* cwp = (const u64*)cw;
    for (int idx = t; idx < 2048; idx += 256) {
        int o = idx >> 5, ip = idx & 31;
        wA[ip * 64 + o] = cwp[o * 32 + ip];
    }
    for (int idx = t; idx < 512; idx += 256) {
        int o = idx >> 3, kp = idx & 7;
        const float2* tp = g_t + ((long)(b * 64 + o) * 256 + xx) * 16;
        float2 v0 = tp[2 * kp], v1 = tp[2 * kp + 1];
        float f0 = (kp == 0) ? 1.f : 2.f;
        wA[(32 + kp) * 64 + o] = pk(f0 * v0.x, 2.f * v1.x);
        wA[(40 + kp) * 64 + o] = pk(f0 * v0.y, 2.f * v1.y);
    }
    const u64* hp = (const u64*)(g_h2[sel]);
    for (int idx = t; idx < 4096; idx += 256) {
        int ip = idx >> 7, yl = idx & 127;
        Bm[ip * 130 + yl] = hp[((long)(b * 32 + ip) * 256 + xx) * 256 + yb + yl];
    }
    for (int idx = t; idx < 2048; idx += 256) {
        int r = idx >> 7, yl = idx & 127;
        int kp = r & 7, y = yb + yl, ky0 = 2 * kp;
        if (r < 8)
            Bm[(32 + kp) * 130 + yl] = pk(g_tyc[ky0 * 256 + y], g_tyc[(ky0 + 1) * 256 + y]);
        else
            Bm[(40 + kp) * 130 + yl] = pk(g_tys[ky0 * 256 + y], g_tys[(ky0 + 1) * 256 + y]);
    }
    if (t < 64) cbs[t] = cb[t];
    __syncthreads();

    int w = t >> 5, lane = t & 31;
    int ob = (w & 3) * 16, yh = (w >> 2) * 64;
    u64 acc[16][2];
#pragma unroll
    for (int oo = 0; oo < 16; oo++) { acc[oo][0] = 0; acc[oo][1] = 0; }

    for (int k = 0; k < 48; k++) {
        u64 b0 = Bm[k * 130 + yh + lane];
        u64 b1 = Bm[k * 130 + yh + 32 + lane];
#pragma unroll
        for (int op = 0; op < 8; op++) {
            u64 a0, a1;
            ldsv2(a0, a1, &wA[k * 64 + ob + 2 * op]);
            acc[2*op  ][0] = fma2(a0, b0, acc[2*op  ][0]);
            acc[2*op  ][1] = fma2(a0, b1, acc[2*op  ][1]);
            acc[2*op+1][0] = fma2(a1, b0, acc[2*op+1][0]);
            acc[2*op+1][1] = fma2(a1, b1, acc[2*op+1][1]);
        }
    }
    __syncthreads();                 // done reading Bm; reuse as output stage
    u64* S = Bm;                     // [32 op][130] u64 = (c0,c1) per y
#pragma unroll
    for (int op = 0; op < 8; op++) {
        int o0 = ob + 2 * op;
        float b0f = cbs[o0], b1f = cbs[o0 + 1];
#pragma unroll
        for (int s = 0; s < 2; s++) {
            int y = yh + s * 32 + lane;
            float2 v0 = unpk(acc[2*op][s]), v1 = unpk(acc[2*op+1][s]);
            float r0 = v0.x + v0.y + b0f, r1 = v1.x + v1.y + b1f;
            if (relu) { r0 = fmaxf(r0, 0.f); r1 = fmaxf(r1, 0.f); }
            S[(o0 >> 1) * 130 + y] = pk(r0, r1);
        }
    }
    __syncthreads();
    u64* ho = (u64*)(g_h2[sel ^ 1]);
    for (int idx = t; idx < 4096; idx += 256) {
        int op = idx >> 7, yl = idx & 127;
        ho[((long)(b * 32 + op) * 256 + xx) * 256 + yb + yl] = S[op * 130 + yl];
    }
}

// ---------------- fused fc1+relu+fc2: K=64 (32 i-pairs), j in 2 halves ------
#define SMEM_FC (32*128*8 + 32*66*8 + 128*4 + 128*4 + 64*4)
__global__ void __launch_bounds__(256) k_fc(int sel, const float* __restrict__ fc1w,
                                            const float* __restrict__ fc1b,
                                            const float* __restrict__ fc2w,
                                            const float* __restrict__ fc2b,
                                            float* __restrict__ out) {
    extern __shared__ float sm[];
    u64* wA = (u64*)sm;                    // [32 ip][128 j]
    u64* Bm = wA + 32 * 128;               // [32 ip][66] (64 y used)
    float* b1s = (float*)(Bm + 32 * 66);   // [128]
    float* f2s = b1s + 128;
    float* sred = f2s + 128;
    int t = threadIdx.x;
    int b = blockIdx.z, xx = blockIdx.y, yb = blockIdx.x * 64;
    int w = t >> 5, lane = t & 31, jblk = w * 16;

    const u64* hp = (const u64*)(g_h2[sel]);
    for (int idx = t; idx < 2048; idx += 256) {
        int ip = idx >> 6, yl = idx & 63;
        Bm[ip * 66 + yl] = hp[((long)(b * 32 + ip) * 256 + xx) * 256 + yb + yl];
    }
    if (t < 64) sred[t] = fc2b[0];
    __syncthreads();

    float p0 = 0.f, p1 = 0.f;
    for (int half = 0; half < 2; half++) {
        int jb0 = half * 128;
        for (int idx = t; idx < 4096; idx += 256) {
            int ip = idx >> 7, j = idx & 127;
            wA[ip * 128 + j] = pk(fc1w[(2 * ip) * 256 + jb0 + j],
                                  fc1w[(2 * ip + 1) * 256 + jb0 + j]);
        }
        if (t < 128) { b1s[t] = fc1b[jb0 + t]; f2s[t] = fc2w[jb0 + t]; }
        __syncthreads();

        u64 acc[16][2];
#pragma unroll
        for (int jj = 0; jj < 16; jj++) { acc[jj][0] = 0; acc[jj][1] = 0; }
        for (int ip = 0; ip < 32; ip++) {
            u64 b0 = Bm[ip * 66 + lane];
            u64 b1 = Bm[ip * 66 + 32 + lane];
#pragma unroll
            for (int op = 0; op < 8; op++) {
                u64 a0, a1;
                ldsv2(a0, a1, &wA[ip * 128 + jblk + 2 * op]);
                acc[2*op  ][0] = fma2(a0, b0, acc[2*op  ][0]);
                acc[2*op  ][1] = fma2(a0, b1, acc[2*op  ][1]);
                acc[2*op+1][0] = fma2(a1, b0, acc[2*op+1][0]);
                acc[2*op+1][1] = fma2(a1, b1, acc[2*op+1][1]);
            }
        }
#pragma unroll
        for (int jj = 0; jj < 16; jj++) {
            float bias = b1s[jblk + jj], f2 = f2s[jblk + jj];
            float2 v0 = unpk(acc[jj][0]), v1 = unpk(acc[jj][1]);
            p0 += fmaxf(v0.x + v0.y + bias, 0.f) * f2;
            p1 += fmaxf(v1.x + v1.y + bias, 0.f) * f2;
        }
        __syncthreads();   // before wA overwrite next half
    }
    atomicAdd(&sred[lane], p0);
    atomicAdd(&sred[32 + lane], p1);
    __syncthreads();
    if (t < 64) out[((long)b * 256 + xx) * 256 + yb + t] = sred[t];
}

// ---------------- launch ----------------
extern "C" void kernel_launch(void* const* d_in, const int* in_sizes, int n_in,
                              void* d_out, int out_size) {
    const float* x    = (const float*)d_in[0];
    const float* fc0w = (const float*)d_in[1];
    const float* fc0b = (const float*)d_in[2];
    const float2* w1  = (const float2*)d_in[3];
    const float2* w2  = (const float2*)d_in[4];
    const float* cw   = (const float*)d_in[5];
    const float* cb   = (const float*)d_in[6];
    const float* fc1w = (const float*)d_in[7];
    const float* fc1b = (const float*)d_in[8];
    const float* fc2w = (const float*)d_in[9];
    const float* fc2b = (const float*)d_in[10];
    float* out = (float*)d_out;

    cudaFuncSetAttribute(k_dfty,  cudaFuncAttributeMaxDynamicSharedMemorySize, SMEM_DFTY);
    cudaFuncSetAttribute(k_final, cudaFuncAttributeMaxDynamicSharedMemorySize, SMEM_FINAL);
    cudaFuncSetAttribute(k_fc,    cudaFuncAttributeMaxDynamicSharedMemorySize, SMEM_FC);

    k_trig<<<48, 256>>>();
    k_wprep<<<(4 * NMODE * M0 * CH * CH) / 256, 256>>>(w1, w2);
    k_lift<<<dim3(SS, NB), 256>>>(x, fc0w, fc0b);

    int cur = 0;
    for (int blk = 0; blk < 4; blk++) {
        k_dfty<<<dim3(32, NB), 256, SMEM_DFTY>>>(cur);
        k_dftx<<<dim3(CH, NB), 512>>>();
        k_mix<<<NMODE * M0, 256>>>(blk);
        k_idftx<<<dim3(CH, NB), 256>>>();
        k_final<<<dim3(2, SS, NB), 256, SMEM_FINAL>>>(cur, cw + (long)blk * CH * CH,
                                                      cb + blk * CH, blk < 3 ? 1 : 0);
        cur ^= 1;
    }
    k_fc<<<dim3(4, SS, NB), 256, SMEM_FC>>>(cur, fc1w, fc1b, fc2w, fc2b, out);
}

// round 9
// speedup vs baseline: 1.5436x; 1.1420x over previous
#include <cuda_runtime.h>

#define NB 16
#define CH 64
#define SS 256
#define M0 16
#define NMODE 32
#define PLANE (SS*SS)

typedef unsigned long long u64;

__device__ __forceinline__ u64 fma2(u64 a, u64 b, u64 c) {
    u64 d; asm("fma.rn.f32x2 %0,%1,%2,%3;" : "=l"(d) : "l"(a), "l"(b), "l"(c)); return d;
}
__device__ __forceinline__ float2 unpk(u64 v) {
    unsigned lo, hi; asm("mov.b64 {%0,%1},%2;" : "=r"(lo), "=r"(hi) : "l"(v));
    return make_float2(__uint_as_float(lo), __uint_as_float(hi));
}
__device__ __forceinline__ u64 pk(float a, float b) {
    u64 d; asm("mov.b64 %0,{%1,%2};" : "=l"(d) : "r"(__float_as_uint(a)), "r"(__float_as_uint(b)));
    return d;
}
__device__ __forceinline__ void ldsv2(u64& a, u64& b, const void* p) {
    unsigned ad = (unsigned)__cvta_generic_to_shared(p);
    asm("ld.shared.v2.u64 {%0,%1},[%2];" : "=l"(a), "=l"(b) : "r"(ad));
}

// ---------------- device scratch ----------------
__device__ float  g_h2[2][NB*32*SS*SS*2];      // [b][c/2][x][y][2]
__device__ float  g_Ar[NB*CH*M0*SS];           // [b][c][ky][x]
__device__ float  g_Ai[NB*CH*M0*SS];
__device__ float2 g_ft[NMODE*M0*NB*CH];        // [mode][b][i]
__device__ float2 g_oft[NMODE*M0*NB*CH];
__device__ float2 g_t [NB*CH*SS*M0];           // [b][o][x][ky]
__device__ float2 g_W [4*NMODE*M0*CH*CH];      // [blk][mode][i][o]
__device__ float  g_tyc[M0*SS];                // cos(2pi ky y/256)
__device__ float  g_tys[M0*SS];                // -sin
__device__ float  g_xc[NMODE*SS];              // cos(2pi kxp x/256)
__device__ float  g_xs[NMODE*SS];              // sin
__device__ float4 g_ty4[M0*SS];                // (c,c,-s,-s)

// ---------------- trig tables ----------------
__global__ void k_trig() {
    int t = blockIdx.x * blockDim.x + threadIdx.x;
    if (t < M0 * SS) {
        int ky = t >> 8, y = t & 255;
        float s, c;
        sincospif((float)(ky * y) / 128.0f, &s, &c);   // exact integer arg
        g_tyc[t] = c; g_tys[t] = -s;
        g_ty4[t] = make_float4(c, c, -s, -s);
    } else if (t < M0 * SS + NMODE * SS) {
        int k = t - M0 * SS;
        int m = k >> 8, x = k & 255;
        int kxp = (m < 16) ? m : (m - 32);
        float s, c;
        sincospif((float)(kxp * x) / 128.0f, &s, &c);
        g_xc[k] = c; g_xs[k] = s;
    }
}

// ---------------- weight re-layout ----------------
__global__ void k_wprep(const float2* __restrict__ w1, const float2* __restrict__ w2) {
    int idx = blockIdx.x * blockDim.x + threadIdx.x;
    int o = idx & 63, i = (idx >> 6) & 63, ky = (idx >> 12) & 15;
    int m = (idx >> 16) & 31, blk = (idx >> 21);
    const float2* src = (m < 16) ? w1 : w2;
    int mx = (m < 16) ? m : (m - 16);
    g_W[idx] = src[((((long)blk * 64 + i) * 64 + o) * 16 + mx) * 16 + ky];
}

// ---------------- lift ----------------
__global__ void k_lift(const float* __restrict__ x, const float* __restrict__ w0,
                       const float* __restrict__ b0) {
    __shared__ float sw[192], sb[64];
    int t = threadIdx.x;
    if (t < 192) sw[t] = w0[t];
    if (t < 64)  sb[t] = b0[t];
    __syncthreads();
    int b = blockIdx.y, xx = blockIdx.x, y = t;
    const float* xp = x + (((long)b * SS + xx) * SS + y) * 3;
    float x0 = xp[0], x1 = xp[1], x2 = xp[2];
    float2* out = (float2*)g_h2[0];
#pragma unroll
    for (int cp = 0; cp < 32; cp++) {
        int c0 = 2 * cp;
        float v0 = x0 * sw[c0]   + x1 * sw[64 + c0]   + x2 * sw[128 + c0]   + sb[c0];
        float v1 = x0 * sw[c0+1] + x1 * sw[64 + c0+1] + x2 * sw[128 + c0+1] + sb[c0+1];
        out[((long)(b * 32 + cp) * SS + xx) * SS + y] = make_float2(v0, v1);
    }
}

// ---------------- forward y-DFT ----------------
// CTA per (cp, xq, b): 128 thr = 4 warps = 4 ky-groups (4 ky each).
// x-tile 64 (lane, lane+32); acc 16 u64; smem sh[y][65x] conflict-free.
#define SMEM_DFTY (32*65*8 + 16*32*16)
__global__ void __launch_bounds__(128) k_dfty(int sel) {
    extern __shared__ float sm[];
    u64* sh = (u64*)sm;                          // [32 y][65 x]
    float4* t4 = (float4*)(sm + 32 * 65 * 2);    // [16 ky][32 y]
    int b = blockIdx.z, xq = blockIdx.y, cp = blockIdx.x, t = threadIdx.x;
    const u64* gp = (const u64*)(g_h2[sel]) + (long)(b * 32 + cp) * PLANE
                  + (long)(xq * 64) * SS;
    int w = t >> 5, lane = t & 31, ky0 = w * 4;
    u64 aR[2][4], aI[2][4];
#pragma unroll
    for (int j = 0; j < 2; j++)
#pragma unroll
        for (int k = 0; k < 4; k++) { aR[j][k] = 0; aI[j][k] = 0; }

    for (int yc = 0; yc < 8; yc++) {
#pragma unroll
        for (int i = 0; i < 16; i++) {
            int idx = i * 128 + t, xx = idx >> 5, yy = idx & 31;
            sh[yy * 65 + xx] = gp[xx * 256 + yc * 32 + yy];
        }
#pragma unroll
        for (int i = 0; i < 4; i++) {
            int idx = i * 128 + t, ky = idx >> 5, yy = idx & 31;
            t4[idx] = g_ty4[ky * 256 + yc * 32 + yy];
        }
        __syncthreads();
#pragma unroll 8
        for (int y = 0; y < 32; y++) {
            u64 h1 = sh[y * 65 + lane], h2v = sh[y * 65 + 32 + lane];
#pragma unroll
            for (int k = 0; k < 4; k++) {
                u64 cc, ss;
                ldsv2(cc, ss, &t4[(ky0 + k) * 32 + y]);
                aR[0][k] = fma2(h1, cc, aR[0][k]);  aI[0][k] = fma2(h1, ss, aI[0][k]);
                aR[1][k] = fma2(h2v, cc, aR[1][k]); aI[1][k] = fma2(h2v, ss, aI[1][k]);
            }
        }
        __syncthreads();
    }
    const float sc = 1.0f / 65536.0f;
#pragma unroll
    for (int j = 0; j < 2; j++) {
        int x = xq * 64 + lane + j * 32;
#pragma unroll
        for (int k = 0; k < 4; k++) {
            int ky = ky0 + k;
            long p0 = ((long)((b * 64 + 2 * cp) * 16 + ky)) * 256 + x;
            long p1 = ((long)((b * 64 + 2 * cp + 1) * 16 + ky)) * 256 + x;
            float2 r = unpk(aR[j][k]), ii = unpk(aI[j][k]);
            g_Ar[p0] = r.x * sc;  g_Ar[p1] = r.y * sc;
            g_Ai[p0] = ii.x * sc; g_Ai[p1] = ii.y * sc;
        }
    }
}

// ---------------- forward x-DFT ----------------
__global__ void __launch_bounds__(512) k_dftx() {
    __shared__ float sAr[16 * 258];
    __shared__ float sAi[16 * 258];
    int b = blockIdx.y, i = blockIdx.x;
    long abase = (long)((b * CH + i) * M0) * SS;
    for (int k = threadIdx.x; k < 4096; k += 512) {
        int ky = k >> 8, x = k & 255;
        sAr[ky * 258 + x] = g_Ar[abase + k];
        sAi[ky * 258 + x] = g_Ai[abase + k];
    }
    __syncthreads();
    int ky = threadIdx.x & 15, m = threadIdx.x >> 4;
    const u64* arp = (const u64*)(sAr + ky * 258);
    const u64* aip = (const u64*)(sAi + ky * 258);
    const u64* cp = (const u64*)(g_xc + m * 256);
    const u64* sp = (const u64*)(g_xs + m * 256);
    u64 RC = 0, IS = 0, IC = 0, RS = 0;
#pragma unroll 8
    for (int xp = 0; xp < 128; xp++) {
        u64 c2 = cp[xp], s2 = sp[xp];
        u64 ar = arp[xp], ai = aip[xp];
        RC = fma2(ar, c2, RC); IS = fma2(ai, s2, IS);
        IC = fma2(ai, c2, IC); RS = fma2(ar, s2, RS);
    }
    float2 rc = unpk(RC), is = unpk(IS), ic = unpk(IC), rs = unpk(RS);
    g_ft[(long)(m * M0 + ky) * (NB * CH) + b * CH + i] =
        make_float2(rc.x + rc.y + is.x + is.y, ic.x + ic.y - rs.x - rs.y);
}

// ---------------- per-mode channel mix ----------------
__global__ void k_mix(int blk) {
    __shared__ float2 F[NB * CH];
    int mode = blockIdx.x;
    const float2* src = g_ft + (long)mode * (NB * CH);
    for (int k = threadIdx.x; k < NB * CH; k += 256) F[k] = src[k];
    __syncthreads();
    const float2* W = g_W + ((long)blk * (NMODE * M0) + mode) * (CH * CH);
    int o = threadIdx.x & 63, bg = threadIdx.x >> 6;
    float accr[4] = {0,0,0,0}, acci[4] = {0,0,0,0};
    for (int i = 0; i < CH; i++) {
        float2 w = W[i * CH + o];
#pragma unroll
        for (int bb = 0; bb < 4; bb++) {
            float2 f = F[(bg * 4 + bb) * CH + i];
            accr[bb] += f.x * w.x - f.y * w.y;
            acci[bb] += f.x * w.y + f.y * w.x;
        }
    }
#pragma unroll
    for (int bb = 0; bb < 4; bb++)
        g_oft[(long)mode * (NB * CH) + (bg * 4 + bb) * CH + o] = make_float2(accr[bb], acci[bb]);
}

// ---------------- inverse x-DFT ----------------
__global__ void k_idftx() {
    __shared__ float2 so[NMODE * M0];
    int b = blockIdx.y, o = blockIdx.x;
    for (int k = threadIdx.x; k < NMODE * M0; k += 256)
        so[k] = g_oft[(long)k * (NB * CH) + b * CH + o];
    __syncthreads();
    int x = threadIdx.x;
    float accr[M0], acci[M0];
#pragma unroll
    for (int ky = 0; ky < M0; ky++) { accr[ky] = 0.f; acci[ky] = 0.f; }
    for (int m = 0; m < NMODE; m++) {
        float c = g_xc[m * 256 + x], s = g_xs[m * 256 + x];
#pragma unroll
        for (int ky = 0; ky < M0; ky++) {
            float2 a = so[m * M0 + ky];
            accr[ky] += a.x * c - a.y * s;
            acci[ky] += a.x * s + a.y * c;
        }
    }
    float2* dst = g_t + ((long)(b * CH + o) * SS + x) * M0;
#pragma unroll
    for (int ky = 0; ky < M0; ky++) dst[ky] = make_float2(accr[ky], acci[ky]);
}

// ---------------- block epilogue: K=96 GEMM, y-tile 64, warp=8 o ----------------
#define SMEM_FINAL (48*64*8 + 48*66*8 + 64*4)
__global__ void __launch_bounds__(256) k_final(int sel, const float* __restrict__ cw,
                                               const float* __restrict__ cb, int relu) {
    extern __shared__ float sm[];
    u64* wA = (u64*)sm;                    // [48 kp][64 o]
    u64* Bm = wA + 48 * 64;                // [48 kp][66] (64 y used)
    float* cbs = (float*)(Bm + 48 * 66);
    int t = threadIdx.x;
    int b = blockIdx.z, xx = blockIdx.y, yb = blockIdx.x * 64;

    const u64* cwp = (const u64*)cw;
    for (int idx = t; idx < 2048; idx += 256) {
        int o = idx >> 5, ip = idx & 31;
        wA[ip * 64 + o] = cwp[o * 32 + ip];
    }
    for (int idx = t; idx < 512; idx += 256) {
        int o = idx >> 3, kp = idx & 7;
        const float2* tp = g_t + ((long)(b * 64 + o) * 256 + xx) * 16;
        float2 v0 = tp[2 * kp], v1 = tp[2 * kp + 1];
        float f0 = (kp == 0) ? 1.f : 2.f;
        wA[(32 + kp) * 64 + o] = pk(f0 * v0.x, 2.f * v1.x);
        wA[(40 + kp) * 64 + o] = pk(f0 * v0.y, 2.f * v1.y);
    }
    const u64* hp = (const u64*)(g_h2[sel]);
    for (int idx = t; idx < 2048; idx += 256) {
        int ip = idx >> 6, yl = idx & 63;
        Bm[ip * 66 + yl] = hp[((long)(b * 32 + ip) * 256 + xx) * 256 + yb + yl];
    }
    for (int idx = t; idx < 1024; idx += 256) {
        int r = idx >> 6, yl = idx & 63;
        int kp = r & 7, y = yb + yl, ky0 = 2 * kp;
        if (r < 8)
            Bm[(32 + kp) * 66 + yl] = pk(g_tyc[ky0 * 256 + y], g_tyc[(ky0 + 1) * 256 + y]);
        else
            Bm[(40 + kp) * 66 + yl] = pk(g_tys[ky0 * 256 + y], g_tys[(ky0 + 1) * 256 + y]);
    }
    if (t < 64) cbs[t] = cb[t];
    __syncthreads();

    int w = t >> 5, lane = t & 31;
    int ob = w * 8;
    u64 acc[8][2];
#pragma unroll
    for (int oo = 0; oo < 8; oo++) { acc[oo][0] = 0; acc[oo][1] = 0; }

    for (int k = 0; k < 48; k++) {
        u64 b0 = Bm[k * 66 + lane];
        u64 b1 = Bm[k * 66 + 32 + lane];
#pragma unroll
        for (int op = 0; op < 4; op++) {
            u64 a0, a1;
            ldsv2(a0, a1, &wA[k * 64 + ob + 2 * op]);
            acc[2*op  ][0] = fma2(a0, b0, acc[2*op  ][0]);
            acc[2*op  ][1] = fma2(a0, b1, acc[2*op  ][1]);
            acc[2*op+1][0] = fma2(a1, b0, acc[2*op+1][0]);
            acc[2*op+1][1] = fma2(a1, b1, acc[2*op+1][1]);
        }
    }
    __syncthreads();                 // done reading Bm; reuse as output stage
    u64* S = Bm;                     // [32 op][66]
#pragma unroll
    for (int op = 0; op < 4; op++) {
        int o0 = ob + 2 * op;
        float b0f = cbs[o0], b1f = cbs[o0 + 1];
#pragma unroll
        for (int s = 0; s < 2; s++) {
            int y = s * 32 + lane;
            float2 v0 = unpk(acc[2*op][s]), v1 = unpk(acc[2*op+1][s]);
            float r0 = v0.x + v0.y + b0f, r1 = v1.x + v1.y + b1f;
            if (relu) { r0 = fmaxf(r0, 0.f); r1 = fmaxf(r1, 0.f); }
            S[(o0 >> 1) * 66 + y] = pk(r0, r1);
        }
    }
    __syncthreads();
    u64* ho = (u64*)(g_h2[sel ^ 1]);
    for (int idx = t; idx < 2048; idx += 256) {
        int op = idx >> 6, yl = idx & 63;
        ho[((long)(b * 32 + op) * 256 + xx) * 256 + yb + yl] = S[op * 66 + yl];
    }
}

// ---------------- fused fc1+relu+fc2: 4 passes of 64 j, warp=8 j ----------------
#define SMEM_FC (32*64*8 + 32*66*8 + 3*64*4)
__global__ void __launch_bounds__(256) k_fc(int sel, const float* __restrict__ fc1w,
                                            const float* __restrict__ fc1b,
                                            const float* __restrict__ fc2w,
                                            const float* __restrict__ fc2b,
                                            float* __restrict__ out) {
    extern __shared__ float sm[];
    u64* wA = (u64*)sm;                    // [32 ip][64 j]
    u64* Bm = wA + 32 * 64;                // [32 ip][66] (64 y used)
    float* b1s = (float*)(Bm + 32 * 66);   // [64]
    float* f2s = b1s + 64;
    float* sred = f2s + 64;
    int t = threadIdx.x;
    int b = blockIdx.z, xx = blockIdx.y, yb = blockIdx.x * 64;
    int w = t >> 5, lane = t & 31, jblk = w * 8;

    const u64* hp = (const u64*)(g_h2[sel]);
    for (int idx = t; idx < 2048; idx += 256) {
        int ip = idx >> 6, yl = idx & 63;
        Bm[ip * 66 + yl] = hp[((long)(b * 32 + ip) * 256 + xx) * 256 + yb + yl];
    }
    if (t < 64) sred[t] = fc2b[0];
    __syncthreads();

    float p0 = 0.f, p1 = 0.f;
    for (int pass = 0; pass < 4; pass++) {
        int jb0 = pass * 64;
        for (int idx = t; idx < 2048; idx += 256) {
            int ip = idx >> 6, j = idx & 63;
            wA[ip * 64 + j] = pk(fc1w[(2 * ip) * 256 + jb0 + j],
                                 fc1w[(2 * ip + 1) * 256 + jb0 + j]);
        }
        if (t < 64) { b1s[t] = fc1b[jb0 + t]; f2s[t] = fc2w[jb0 + t]; }
        __syncthreads();

        u64 acc[8][2];
#pragma unroll
        for (int jj = 0; jj < 8; jj++) { acc[jj][0] = 0; acc[jj][1] = 0; }
        for (int ip = 0; ip < 32; ip++) {
            u64 b0 = Bm[ip * 66 + lane];
            u64 b1 = Bm[ip * 66 + 32 + lane];
#pragma unroll
            for (int op = 0; op < 4; op++) {
                u64 a0, a1;
                ldsv2(a0, a1, &wA[ip * 64 + jblk + 2 * op]);
                acc[2*op  ][0] = fma2(a0, b0, acc[2*op  ][0]);
                acc[2*op  ][1] = fma2(a0, b1, acc[2*op  ][1]);
                acc[2*op+1][0] = fma2(a1, b0, acc[2*op+1][0]);
                acc[2*op+1][1] = fma2(a1, b1, acc[2*op+1][1]);
            }
        }
#pragma unroll
        for (int jj = 0; jj < 8; jj++) {
            float bias = b1s[jblk + jj], f2 = f2s[jblk + jj];
            float2 v0 = unpk(acc[jj][0]), v1 = unpk(acc[jj][1]);
            p0 += fmaxf(v0.x + v0.y + bias, 0.f) * f2;
            p1 += fmaxf(v1.x + v1.y + bias, 0.f) * f2;
        }
        __syncthreads();   // before wA overwrite next pass
    }
    atomicAdd(&sred[lane], p0);
    atomicAdd(&sred[32 + lane], p1);
    __syncthreads();
    if (t < 64) out[((long)b * 256 + xx) * 256 + yb + t] = sred[t];
}

// ---------------- launch ----------------
extern "C" void kernel_launch(void* const* d_in, const int* in_sizes, int n_in,
                              void* d_out, int out_size) {
    const float* x    = (const float*)d_in[0];
    const float* fc0w = (const float*)d_in[1];
    const float* fc0b = (const float*)d_in[2];
    const float2* w1  = (const float2*)d_in[3];
    const float2* w2  = (const float2*)d_in[4];
    const float* cw   = (const float*)d_in[5];
    const float* cb   = (const float*)d_in[6];
    const float* fc1w = (const float*)d_in[7];
    const float* fc1b = (const float*)d_in[8];
    const float* fc2w = (const float*)d_in[9];
    const float* fc2b = (const float*)d_in[10];
    float* out = (float*)d_out;

    cudaFuncSetAttribute(k_dfty,  cudaFuncAttributeMaxDynamicSharedMemorySize, SMEM_DFTY);
    cudaFuncSetAttribute(k_final, cudaFuncAttributeMaxDynamicSharedMemorySize, SMEM_FINAL);
    cudaFuncSetAttribute(k_fc,    cudaFuncAttributeMaxDynamicSharedMemorySize, SMEM_FC);

    k_trig<<<48, 256>>>();
    k_wprep<<<(4 * NMODE * M0 * CH * CH) / 256, 256>>>(w1, w2);
    k_lift<<<dim3(SS, NB), 256>>>(x, fc0w, fc0b);

    int cur = 0;
    for (int blk = 0; blk < 4; blk++) {
        k_dfty<<<dim3(32, 4, NB), 128, SMEM_DFTY>>>(cur);
        k_dftx<<<dim3(CH, NB), 512>>>();
        k_mix<<<NMODE * M0, 256>>>(blk);
        k_idftx<<<dim3(CH, NB), 256>>>();
        k_final<<<dim3(4, SS, NB), 256, SMEM_FINAL>>>(cur, cw + (long)blk * CH * CH,
                                                      cb + blk * CH, blk < 3 ? 1 : 0);
        cur ^= 1;
    }
    k_fc<<<dim3(4, SS, NB), 256, SMEM_FC>>>(cur, fc1w, fc1b, fc2w, fc2b, out);
}